// round 17
// baseline (speedup 1.0000x reference)
#include <cuda_runtime.h>

#define N_NODES 50000
#define N_EDGES 800000

// ---------------- scratch (static device globals; no allocations) ----------------
__device__ __align__(16) float g_tab[576];                    // al|ar|ae|k1|cl (5x64), u2(128)@320, v2(128)@448
__device__ __align__(16) float g_den1[N_NODES * 8];
__device__ __align__(16) float g_num1[N_NODES * 8];
__device__ __align__(16) float g_xl2[(size_t)N_NODES * 128];  // 25.6 MB
__device__ __align__(16) float g_xr2[(size_t)N_NODES * 128];  // 25.6 MB
__device__ __align__(16) float g_s[N_NODES];
__device__ __align__(16) float g_t[N_NODES];
// CSR by destination (segments contiguous per node; segment ORDER is arbitrary)
__device__ int   g_cnt[N_NODES];
__device__ int   g_fill[N_NODES];
__device__ int   g_rowbeg[N_NODES];
__device__ int   g_total;
__device__ int   g_esrc[N_EDGES];                             // src node per CSR slot
__device__ __align__(16) float g_ea[N_EDGES];                 // edge_attr per CSR slot

// ---------------- kernel 0: zero counters (blocks 0..nzb-1) + derived rank-1 vectors (last block) ----------------
__global__ __launch_bounds__(256) void k_init(const float* __restrict__ W_em, const float* __restrict__ b_em,
                                              const float* __restrict__ W0,   const float* __restrict__ b0,
                                              const float* __restrict__ Wl1,  const float* __restrict__ bl1,
                                              const float* __restrict__ Wr1,  const float* __restrict__ br1,
                                              const float* __restrict__ We1,  const float* __restrict__ We2,
                                              int n, int nzb) {
    int b = blockIdx.x;
    int tid = threadIdx.x;
    if (b < nzb) {                       // zero part
        int i = b * 256 + tid;
        if (i < n) { g_cnt[i] = 0; g_fill[i] = 0; }
        if (i == 0) g_total = 0;
        return;
    }
    // derive part (one block, threads 0..127)
    if (tid >= 128) return;
    int c = tid;
    if (c < 64) {
        float al = 0.f, cl = 0.f, ar = 0.f, cr = 0.f, ae = 0.f, ce = 0.f;
        for (int j = 0; j < 128; j++) {
            float w0 = W0[j], bb = b0[j], we = W_em[j], be = b_em[j];
            float l = Wl1[j * 64 + c], r = Wr1[j * 64 + c], ev = We1[j * 64 + c];
            al = fmaf(w0, l, al); cl = fmaf(bb, l, cl);
            ar = fmaf(w0, r, ar); cr = fmaf(bb, r, cr);
            ae = fmaf(we, ev, ae); ce = fmaf(be, ev, ce);
        }
        cl += bl1[c]; cr += br1[c];
        g_tab[c]       = al;
        g_tab[64 + c]  = ar;
        g_tab[128 + c] = ae;
        g_tab[192 + c] = cl + cr + ce;   // constant inside leaky_relu
        g_tab[256 + c] = cl;             // out1 = al*S1 + cl*S0
    }
    float u = 0.f, v = 0.f;
    for (int j = 0; j < 128; j++) {
        float w = We2[j * 128 + c];
        u = fmaf(W_em[j], w, u);
        v = fmaf(b_em[j], w, v);
    }
    g_tab[320 + c] = u;
    g_tab[448 + c] = v;
}

// ---------------- CSR build ----------------
__global__ void k_count(const int* __restrict__ ei, int E) {
    int e = blockIdx.x * blockDim.x + threadIdx.x;
    if (e < E) atomicAdd(&g_cnt[ei[E + e]], 1);
}

// warp-aggregated segment allocation: contiguous per-node ranges, order arbitrary.
__global__ __launch_bounds__(256) void k_alloc(int n) {
    int i = blockIdx.x * blockDim.x + threadIdx.x;
    int lane = threadIdx.x & 31;
    int v = (i < n) ? g_cnt[i] : 0;
    int incl = v;
#pragma unroll
    for (int o = 1; o < 32; o <<= 1) {
        int t = __shfl_up_sync(0xffffffffu, incl, o);
        if (lane >= o) incl += t;
    }
    int base = 0;
    if (lane == 31) base = atomicAdd(&g_total, incl);   // one atomic per warp
    base = __shfl_sync(0xffffffffu, base, 31);
    if (i < n) g_rowbeg[i] = base + incl - v;           // exclusive offset within warp chunk
}

__global__ void k_scatter(const int* __restrict__ ei, const float* __restrict__ eattr, int E) {
    int e = blockIdx.x * blockDim.x + threadIdx.x;
    if (e >= E) return;
    int dst = ei[E + e];
    int pos = g_rowbeg[dst] + atomicAdd(&g_fill[dst], 1);
    g_esrc[pos] = ei[e];
    g_ea[pos]   = eattr[e];
}

// ---------------- layer 1 fused: online softmax per (node, head) lane ----------------
__global__ __launch_bounds__(256) void k_seg1(const float* __restrict__ x,
                                              const float* __restrict__ att1, int N) {
    int gl = blockIdx.x * blockDim.x + threadIdx.x;  // lane id in [0, N*8)
    int node = gl >> 3;
    int head = gl & 7;
    if (node >= N) return;
    // coefficients for this head (8 channels) in registers
    float al[8], ar[8], ae[8], k1[8], at[8];
#pragma unroll
    for (int c = 0; c < 8; c++) {
        int i = head * 8 + c;
        al[c] = g_tab[i];
        ar[c] = g_tab[64 + i];
        ae[c] = g_tab[128 + i];
        k1[c] = g_tab[192 + i];
        at[c] = att1[i];
    }
    float xd = x[node];
    int beg = g_rowbeg[node], end = beg + g_cnt[node];
    float mx = -1e30f, den = 0.f, num = 0.f;
    for (int j = beg; j < end; j++) {
        int s = g_esrc[j];
        float ea = g_ea[j];
        float xs = x[s];
        float a = 0.f;
#pragma unroll
        for (int c = 0; c < 8; c++) {
            float z = fmaf(xs, al[c], fmaf(xd, ar[c], fmaf(ea, ae[c], k1[c])));
            z = z > 0.f ? z : 0.2f * z;
            a = fmaf(z, at[c], a);
        }
        if (a <= mx) {                       // fast path: no rescale
            float ex = __expf(a - mx);
            den += ex;
            num = fmaf(ex, xs, num);
        } else {                             // rescale; new term has ex = 1 exactly
            float corr = __expf(mx - a);     // 0 on first edge (mx = -1e30)
            den = fmaf(den, corr, 1.f);
            num = fmaf(num, corr, xs);
            mx = a;
        }
    }
    g_den1[node * 8 + head] = den;
    g_num1[node * 8 + head] = num;
}

// ---------------- node pass: h1 = ELU(out1), then xl2/xr2 = h1 @ Wl2/Wr2 ----------------
__global__ __launch_bounds__(256) void k_node1(const float* __restrict__ Wl2, const float* __restrict__ bl2,
                                               const float* __restrict__ Wr2, const float* __restrict__ br2,
                                               const float* __restrict__ bias1, int N) {
    __shared__ float4 s_h4[128 * 16];                         // 128 nodes x 64 channels, float4 view
    __shared__ float s_al[64], s_cl[64], s_b1[64];
    float* s_h = (float*)s_h4;
    int tid = threadIdx.x;
    if (tid < 64) { s_al[tid] = g_tab[tid]; s_cl[tid] = g_tab[256 + tid]; s_b1[tid] = bias1[tid]; }
    int half = tid >> 7, k = tid & 127;
    const float* W = half ? Wr2 : Wl2;
    float bcol = half ? br2[k] : bl2[k];
    float wreg[64];
#pragma unroll
    for (int j = 0; j < 64; j++) wreg[j] = W[j * 128 + k];   // weight column in registers
    __syncthreads();
    int n0 = blockIdx.x * 128;
    int nt = min(128, N - n0);
    for (int idx = tid; idx < nt * 64; idx += 256) {
        int nl = idx >> 6, hc = idx & 63, h = hc >> 3;
        int n = n0 + nl;
        float den = g_den1[(size_t)n * 8 + h];
        float dm = fmaxf(den, 1e-16f);
        float S1 = g_num1[(size_t)n * 8 + h] / dm;
        float S0 = den / dm;                                  // 1 if node has edges, else 0
        float o = fmaf(s_al[hc], S1, s_cl[hc] * S0) + s_b1[hc];
        s_h[idx] = o > 0.f ? o : expm1f(o);                   // ELU
    }
    __syncthreads();
    float* dst = half ? g_xr2 : g_xl2;
    for (int nl = 0; nl < nt; nl++) {
        const float4* row = &s_h4[nl * 16];
        float acc = bcol;
#pragma unroll
        for (int j4 = 0; j4 < 16; j4++) {                     // LDS.128 broadcast: 16 loads not 64
            float4 h = row[j4];
            acc = fmaf(h.x, wreg[4 * j4],     acc);
            acc = fmaf(h.y, wreg[4 * j4 + 1], acc);
            acc = fmaf(h.z, wreg[4 * j4 + 2], acc);
            acc = fmaf(h.w, wreg[4 * j4 + 3], acc);
        }
        dst[(size_t)(n0 + nl) * 128 + k] = acc;
    }
}

// ---------------- layer 2 fused: warp per node, online softmax, epilogue -> s,t ----------------
__global__ __launch_bounds__(256) void k_seg2(const float* __restrict__ att2,
                                              const float* __restrict__ bias2,
                                              const float* __restrict__ Wd, int N) {
    int wid = (blockIdx.x * blockDim.x + threadIdx.x) >> 5;
    int lane = threadIdx.x & 31;
    if (wid >= N) return;
    int n = wid;
    int c = lane * 4;
    float4 u2  = *(const float4*)&g_tab[320 + c];
    float4 v2  = *(const float4*)&g_tab[448 + c];
    float4 at  = *(const float4*)&att2[c];
    float4 xr  = *(const float4*)&g_xr2[(size_t)n * 128 + c];
    float4 xrv = make_float4(xr.x + v2.x, xr.y + v2.y, xr.z + v2.z, xr.w + v2.w);
    int beg = g_rowbeg[n], end = beg + g_cnt[n];
    float mx = -1e30f, den = 0.f;
    float4 acc = make_float4(0.f, 0.f, 0.f, 0.f);
    for (int j = beg; j < end; j++) {
        int s = g_esrc[j];          // broadcast loads (same addr across warp)
        float ea = g_ea[j];
        float4 xl = *(const float4*)&g_xl2[(size_t)s * 128 + c];
        float z0 = xl.x + fmaf(ea, u2.x, xrv.x); z0 = z0 > 0.f ? z0 : 0.2f * z0;
        float z1 = xl.y + fmaf(ea, u2.y, xrv.y); z1 = z1 > 0.f ? z1 : 0.2f * z1;
        float z2 = xl.z + fmaf(ea, u2.z, xrv.z); z2 = z2 > 0.f ? z2 : 0.2f * z2;
        float z3 = xl.w + fmaf(ea, u2.w, xrv.w); z3 = z3 > 0.f ? z3 : 0.2f * z3;
        float p = fmaf(z0, at.x, fmaf(z1, at.y, fmaf(z2, at.z, z3 * at.w)));
#pragma unroll
        for (int o = 16; o > 0; o >>= 1) p += __shfl_xor_sync(0xffffffffu, p, o);
        if (p <= mx) {                       // fast path (warp-uniform): no rescale
            float ex = __expf(p - mx);
            den += ex;
            acc.x = fmaf(ex, xl.x, acc.x);
            acc.y = fmaf(ex, xl.y, acc.y);
            acc.z = fmaf(ex, xl.z, acc.z);
            acc.w = fmaf(ex, xl.w, acc.w);
        } else {                             // rescale; new term has ex = 1 exactly
            float corr = __expf(mx - p);     // 0 on first edge
            den   = fmaf(den, corr, 1.f);
            acc.x = fmaf(acc.x, corr, xl.x);
            acc.y = fmaf(acc.y, corr, xl.y);
            acc.z = fmaf(acc.z, corr, xl.z);
            acc.w = fmaf(acc.w, corr, xl.w);
            mx = p;
        }
    }
    float inv = 1.f / fmaxf(den, 1e-16f);
    float4 b2 = *(const float4*)&bias2[c];
    float4 w0 = *(const float4*)&Wd[c];
    float4 w1 = *(const float4*)&Wd[128 + c];
    float h0 = fmaf(acc.x, inv, b2.x), h1 = fmaf(acc.y, inv, b2.y);
    float h2 = fmaf(acc.z, inv, b2.z), h3 = fmaf(acc.w, inv, b2.w);
    float sa = fmaf(h0, w0.x, fmaf(h1, w0.y, fmaf(h2, w0.z, h3 * w0.w)));
    float ta = fmaf(h0, w1.x, fmaf(h1, w1.y, fmaf(h2, w1.z, h3 * w1.w)));
#pragma unroll
    for (int o = 16; o > 0; o >>= 1) {
        sa += __shfl_xor_sync(0xffffffffu, sa, o);
        ta += __shfl_xor_sync(0xffffffffu, ta, o);
    }
    if (lane == 0) { g_s[n] = sa; g_t[n] = ta; }
}

// ---------------- final: out[e] = s[src] + t[dst] + bd ----------------
__global__ __launch_bounds__(256) void k_final(const int* __restrict__ ei,
                                               const float* __restrict__ bd,
                                               float* __restrict__ out, int E) {
    int e = blockIdx.x * blockDim.x + threadIdx.x;
    if (e >= E) return;
    out[e] = g_s[ei[e]] + g_t[ei[E + e]] + bd[0];
}

// ---------------- launch ----------------
extern "C" void kernel_launch(void* const* d_in, const int* in_sizes, int n_in,
                              void* d_out, int out_size) {
    const float* x     = (const float*)d_in[0];
    const int*   ei    = (const int*)d_in[1];      // int32 (JAX x64 disabled)
    const float* eattr = (const float*)d_in[2];
    const float* W_em = (const float*)d_in[3];  const float* b_em = (const float*)d_in[4];
    const float* W0   = (const float*)d_in[5];  const float* b0   = (const float*)d_in[6];
    const float* Wl1  = (const float*)d_in[7];  const float* bl1  = (const float*)d_in[8];
    const float* Wr1  = (const float*)d_in[9];  const float* br1  = (const float*)d_in[10];
    const float* We1  = (const float*)d_in[11]; const float* att1 = (const float*)d_in[12];
    const float* bias1= (const float*)d_in[13];
    const float* Wl2  = (const float*)d_in[14]; const float* bl2  = (const float*)d_in[15];
    const float* Wr2  = (const float*)d_in[16]; const float* br2  = (const float*)d_in[17];
    const float* We2  = (const float*)d_in[18]; const float* att2 = (const float*)d_in[19];
    const float* bias2= (const float*)d_in[20];
    const float* Wd   = (const float*)d_in[21]; const float* bd   = (const float*)d_in[22];
    int N = in_sizes[0];          // x is [N,1]
    int E = in_sizes[2];          // edge_attr is [E,1]
    float* out = (float*)d_out;

    int nzb = (N + 255) / 256;    // zero blocks; +1 block for derive
    k_init<<<nzb + 1, 256>>>(W_em, b_em, W0, b0, Wl1, bl1, Wr1, br1, We1, We2, N, nzb);
    k_count<<<(E + 255) / 256, 256>>>(ei, E);
    k_alloc<<<(N + 255) / 256, 256>>>(N);
    k_scatter<<<(E + 255) / 256, 256>>>(ei, eattr, E);
    k_seg1<<<(N * 8 + 255) / 256, 256>>>(x, att1, N);
    k_node1<<<(N + 127) / 128, 256>>>(Wl2, bl2, Wr2, br2, bias1, N);
    k_seg2<<<(N + 7) / 8, 256>>>(att2, bias2, Wd, N);
    k_final<<<(E + 255) / 256, 256>>>(ei, bd, out, E);
}